// round 7
// baseline (speedup 1.0000x reference)
#include <cuda_runtime.h>
#include <cuda_bf16.h>
#include <cstdint>

// PrRoIPool2D(7,7, spatial_scale=0.5)
// features: (8, 256, 56, 56) f32 ; rois: (256,5) ; out: (256,256,7,7) f32

#define POOLED 7
#define SCALE 0.5f
#define CC 256
#define HH 56
#define WW 56
#define RMAX 256
#define NG 8            // staged float4 groups per channel-row (32 floats >= 7bw+5)
#define NSTR 9          // smem layout stride in float4 (conflict-free LDS.128)
#define NCHS 32         // channels per CTA slab
#define NTHR 128        // 32 channels x 4 pw-pair groups

// ---- precomputed per-ROI tables ----
__device__ __align__(16) float g_ixw[RMAX][4][2][12]; // pair g, bin{2g,2g+1}, 12 taps
__device__ __align__(16) float g_iyT[RMAX][28][8];    // per-row (h-hlo): iy[7]*(1/area), pad
__device__ __align__(16) int   g_meta[RMAX][8];       // b, hlo, hhi, base4, prel[4]

__device__ __forceinline__ float tentG(float t) {
    float u;
    if (t <= 0.0f) { u = t + 1.0f; return 0.5f * u * u; }
    u = 1.0f - t;
    return 1.0f - 0.5f * u * u;
}
__device__ __forceinline__ float tent_int(float s, float e, float i) {
    float a = fminf(fmaxf(s - i, -1.0f), 1.0f);
    float b = fminf(fmaxf(e - i, -1.0f), 1.0f);
    return tentG(b) - tentG(a);
}

// ---------------- setup: one 32-thread block per ROI ----------------
__global__ void setup_kernel(const float* __restrict__ rois, int R) {
    const int r = blockIdx.x;
    if (r >= R) return;
    const int t = threadIdx.x;

    const float rb  = rois[r * 5 + 0];
    const float rx1 = rois[r * 5 + 1] * SCALE;
    const float ry1 = rois[r * 5 + 2] * SCALE;
    const float rx2 = rois[r * 5 + 3] * SCALE;
    const float ry2 = rois[r * 5 + 4] * SCALE;
    const float bw = (rx2 - rx1) * (1.0f / POOLED);
    const float bh = (ry2 - ry1) * (1.0f / POOLED);
    const float area = bw * bh;
    const float sc = (area > 0.0f) ? (1.0f / fmaxf(area, 1e-12f)) : 0.0f;

    int wlo = (int)ceilf(rx1 - 1.0f); if (wlo < 0) wlo = 0;
    const int base4 = (wlo & ~3) >> 2;                    // <= 13
    int hlo = (int)ceilf(ry1 - 1.0f);  if (hlo < 0) hlo = 0;
    int hhi = (int)floorf(ry2 + 1.0f); if (hhi > HH - 1) hhi = HH - 1;
    if (hhi < hlo) hhi = hlo;

    // per-pair relative float4 offset within staged window (bounded <= 5)
    int prel[4];
#pragma unroll
    for (int g = 0; g < 4; ++g) {
        const float xs = rx1 + (2 * g) * bw;
        int pb = (int)ceilf(xs - 1.0f); if (pb < 0) pb = 0;
        int pb4 = (pb & ~3) >> 2; if (pb4 > 13) pb4 = 13;
        int rel = pb4 - base4;
        if (rel < 0) rel = 0;
        if (rel > 5) rel = 5;      // window rel..rel+2 fits NG=8 slots
        prel[g] = rel;
    }

    // x weights: 4 pairs x 2 bins x 12 taps (absolute w = (base4+prel)*4 + k)
    for (int e = t; e < 4 * 2 * 12; e += 32) {
        const int g = e / 24, rem = e - g * 24, bin = rem / 12, k = rem - bin * 12;
        const int q = 2 * g + bin;
        float v = 0.0f;
        if (q < POOLED) {
            const int w = (base4 + prel[g]) * 4 + k;
            if (w < WW) {
                const float xs = rx1 + q * bw;
                v = tent_int(xs, xs + bw, (float)w);
            }
        }
        g_ixw[r][g][bin][k] = v;
    }
    // y weights transposed: row-major by (h - hlo), 1/area folded
    for (int e = t; e < 28 * 8; e += 32) {
        const int hr = e >> 3, j = e & 7;
        const int h = hlo + hr;
        float v = 0.0f;
        if (j < POOLED && h <= hhi) {
            const float ys = ry1 + j * bh;
            v = sc * tent_int(ys, ys + bh, (float)h);
        }
        g_iyT[r][hr][j] = v;
    }
    if (t == 0) {
        g_meta[r][0] = (int)rb;
        g_meta[r][1] = hlo;
        g_meta[r][2] = hhi;
        g_meta[r][3] = base4;
        g_meta[r][4] = prel[0]; g_meta[r][5] = prel[1];
        g_meta[r][6] = prel[2]; g_meta[r][7] = prel[3];
    }
}

// ---------------- cp.async helpers ----------------
__device__ __forceinline__ void cpa16(uint32_t dst, const void* src) {
    asm volatile("cp.async.ca.shared.global [%0], [%1], 16;\n" :: "r"(dst), "l"(src));
}
__device__ __forceinline__ void cpa_commit() {
    asm volatile("cp.async.commit_group;\n");
}
template<int N>
__device__ __forceinline__ void cpa_wait() {
    asm volatile("cp.async.wait_group %0;\n" :: "n"(N));
}

// ---------------- main: 128 thr = 32 ch x 4 pw-pairs; grid = R*8 ----------------
__global__ __launch_bounds__(NTHR, 6)
void prroi_main(const float* __restrict__ feat, float* __restrict__ out) {
    const int bid = blockIdx.x;
    const int r    = bid >> 3;
    const int c0   = (bid & 7) << 5;          // 32-channel slab
    const int tid  = threadIdx.x;
    const int cl   = tid & 31;                // channel lane
    const int g    = tid >> 5;                // pw-pair group == warp id

    __shared__ float4 sbuf[3][NCHS * NSTR];   // 3 x 288 x 16B = 13824 B

    const int4 m0 = __ldg((const int4*)&g_meta[r][0]);
    const int b = m0.x, hlo = m0.y, hhi = m0.z, base4 = m0.w;
    const int4 m1 = __ldg((const int4*)&g_meta[r][4]);
    const int prel = (g == 0) ? m1.x : (g == 1) ? m1.y : (g == 2) ? m1.z : m1.w;

    // hoist pair weights (2 bins x 12 taps) into registers (warp-uniform -> broadcast)
    float4 w0[3], w1[3];
    {
        const float4* wp = (const float4*)&g_ixw[r][g][0][0];
        w0[0] = __ldg(wp);     w0[1] = __ldg(wp + 1); w0[2] = __ldg(wp + 2);
        w1[0] = __ldg(wp + 3); w1[1] = __ldg(wp + 4); w1[2] = __ldg(wp + 5);
    }

    // staging: 256 slots (32 ch x 8 groups) in layout stride 9; 2 cp.async per thread
    const int c_lo = tid >> 3;                 // 0..15
    const int jj   = tid & 7;                  // group
    int i4 = base4 + jj; if (i4 > 13) i4 = 13; // clamp; weights are 0 for w>=56
    const float* s0p = feat + (size_t)(b * CC + c0 + c_lo) * (HH * WW) + i4 * 4;
    const float* s1p = s0p + 16 * (HH * WW);
    const uint32_t d0a = (uint32_t)__cvta_generic_to_shared(&sbuf[0][c_lo * NSTR + jj]);
    const uint32_t d1a = (uint32_t)__cvta_generic_to_shared(&sbuf[0][(c_lo + 16) * NSTR + jj]);
    const uint32_t bufB = NCHS * NSTR * 16;    // bytes per buffer

    // prologue: stage rows hlo, hlo+1 (clamped) into buffers 0,1
    {
        cpa16(d0a, s0p + hlo * WW);
        cpa16(d1a, s1p + hlo * WW);
        cpa_commit();
        int h1 = hlo + 1; if (h1 > hhi) h1 = hhi;
        cpa16(d0a + bufB, s0p + h1 * WW);
        cpa16(d1a + bufB, s1p + h1 * WW);
        cpa_commit();
    }

    float acc0[POOLED], acc1[POOLED];
#pragma unroll
    for (int k = 0; k < POOLED; ++k) { acc0[k] = 0.0f; acc1[k] = 0.0f; }

    int p = 0;
    for (int h = hlo; h <= hhi; ++h) {
        cpa_wait<1>();        // row h's group complete (2 groups were ahead)
        __syncthreads();      // make it visible block-wide

        const float4 ya = __ldg((const float4*)&g_iyT[r][h - hlo][0]);
        const float4 yb = __ldg((const float4*)&g_iyT[r][h - hlo][4]);

        // 12-tap pair window (3x LDS.128, phase-conflict-free via stride 9)
        const float4* xv = &sbuf[p][cl * NSTR + prel];
        const float4 x0 = xv[0], x1 = xv[1], x2 = xv[2];

        float s0 = 0.0f, s1 = 0.0f;
        s0 = fmaf(x0.x, w0[0].x, s0); s0 = fmaf(x0.y, w0[0].y, s0);
        s0 = fmaf(x0.z, w0[0].z, s0); s0 = fmaf(x0.w, w0[0].w, s0);
        s0 = fmaf(x1.x, w0[1].x, s0); s0 = fmaf(x1.y, w0[1].y, s0);
        s0 = fmaf(x1.z, w0[1].z, s0); s0 = fmaf(x1.w, w0[1].w, s0);
        s0 = fmaf(x2.x, w0[2].x, s0); s0 = fmaf(x2.y, w0[2].y, s0);
        s0 = fmaf(x2.z, w0[2].z, s0); s0 = fmaf(x2.w, w0[2].w, s0);

        s1 = fmaf(x0.x, w1[0].x, s1); s1 = fmaf(x0.y, w1[0].y, s1);
        s1 = fmaf(x0.z, w1[0].z, s1); s1 = fmaf(x0.w, w1[0].w, s1);
        s1 = fmaf(x1.x, w1[1].x, s1); s1 = fmaf(x1.y, w1[1].y, s1);
        s1 = fmaf(x1.z, w1[1].z, s1); s1 = fmaf(x1.w, w1[1].w, s1);
        s1 = fmaf(x2.x, w1[2].x, s1); s1 = fmaf(x2.y, w1[2].y, s1);
        s1 = fmaf(x2.z, w1[2].z, s1); s1 = fmaf(x2.w, w1[2].w, s1);

        // y accumulation; zero rows skipped (uniform branches, no divergence)
        if (ya.x != 0.0f) { acc0[0] = fmaf(ya.x, s0, acc0[0]); acc1[0] = fmaf(ya.x, s1, acc1[0]); }
        if (ya.y != 0.0f) { acc0[1] = fmaf(ya.y, s0, acc0[1]); acc1[1] = fmaf(ya.y, s1, acc1[1]); }
        if (ya.z != 0.0f) { acc0[2] = fmaf(ya.z, s0, acc0[2]); acc1[2] = fmaf(ya.z, s1, acc1[2]); }
        if (ya.w != 0.0f) { acc0[3] = fmaf(ya.w, s0, acc0[3]); acc1[3] = fmaf(ya.w, s1, acc1[3]); }
        if (yb.x != 0.0f) { acc0[4] = fmaf(yb.x, s0, acc0[4]); acc1[4] = fmaf(yb.x, s1, acc1[4]); }
        if (yb.y != 0.0f) { acc0[5] = fmaf(yb.y, s0, acc0[5]); acc1[5] = fmaf(yb.y, s1, acc1[5]); }
        if (yb.z != 0.0f) { acc0[6] = fmaf(yb.z, s0, acc0[6]); acc1[6] = fmaf(yb.z, s1, acc1[6]); }

        // prefetch row h+2 into buffer (p+2)%3 (disjoint from buffers in use)
        int nr = h + 2; if (nr > hhi) nr = hhi;
        int np = p + 2; if (np >= 3) np -= 3;
        cpa16(d0a + (uint32_t)np * bufB, s0p + nr * WW);
        cpa16(d1a + (uint32_t)np * bufB, s1p + nr * WW);
        cpa_commit();

        p = (p + 1 == 3) ? 0 : p + 1;
    }

    // drain outstanding async copies before reusing smem for output gather
    cpa_wait<0>();
    __syncthreads();

    // ---- gather to smem, write coalesced ----
    float* sout = (float*)&sbuf[0][0];        // 3456 floats >= 1568
    const int pw0 = 2 * g;
#pragma unroll
    for (int ph = 0; ph < POOLED; ++ph) {
        sout[cl * 49 + ph * 7 + pw0] = acc0[ph];
        if (pw0 + 1 < POOLED) sout[cl * 49 + ph * 7 + pw0 + 1] = acc1[ph];
    }
    __syncthreads();

    float4* o4 = (float4*)(out + ((size_t)r * CC + c0) * 49);
    const float4* s4 = (const float4*)sout;
#pragma unroll
    for (int k = 0; k < 3; ++k)
        o4[tid + NTHR * k] = s4[tid + NTHR * k];       // 384 float4
    if (tid < 8) o4[384 + tid] = s4[384 + tid];        // -> 392 = 1568 floats
}

extern "C" void kernel_launch(void* const* d_in, const int* in_sizes, int n_in,
                              void* d_out, int out_size) {
    const float* feat = (const float*)d_in[0];
    const float* rois = (const float*)d_in[1];
    float* out = (float*)d_out;
    int R = in_sizes[1] / 5;
    if (R > RMAX) R = RMAX;
    setup_kernel<<<R, 32>>>(rois, R);
    prroi_main<<<R * 8, NTHR>>>(feat, out);
}

// round 8
// speedup vs baseline: 1.0691x; 1.0691x over previous
#include <cuda_runtime.h>
#include <cuda_bf16.h>
#include <cstdint>

// PrRoIPool2D(7,7, spatial_scale=0.5)
// features: (8, 256, 56, 56) f32 ; rois: (256,5) ; out: (256,256,7,7) f32

#define POOLED 7
#define SCALE 0.5f
#define CC 256
#define HH 56
#define WW 56
#define RMAX 256
#define NG 8            // staged float4 groups per channel-row (32 floats >= 7bw+5)
#define NSTR 9          // smem layout stride in float4 (conflict-free LDS.128)
#define NCHS 32         // channels per CTA slab
#define NTHR 128        // 32 channels x 4 pw-pair groups

// ---- precomputed per-ROI tables ----
__device__ __align__(16) float g_ixw[RMAX][4][2][12]; // pair g, bin{2g,2g+1}, 12 taps
__device__ __align__(16) float g_iyT[RMAX][28][8];    // per-row (h-hlo): iy[7]*(1/area), pad
__device__ __align__(16) int   g_meta[RMAX][8];       // b, hlo, hhi, base4, prel[4]

__device__ __forceinline__ float tentG(float t) {
    float u;
    if (t <= 0.0f) { u = t + 1.0f; return 0.5f * u * u; }
    u = 1.0f - t;
    return 1.0f - 0.5f * u * u;
}
__device__ __forceinline__ float tent_int(float s, float e, float i) {
    float a = fminf(fmaxf(s - i, -1.0f), 1.0f);
    float b = fminf(fmaxf(e - i, -1.0f), 1.0f);
    return tentG(b) - tentG(a);
}

// ---------------- setup: one 32-thread block per ROI ----------------
__global__ void setup_kernel(const float* __restrict__ rois, int R) {
    const int r = blockIdx.x;
    if (r >= R) return;
    const int t = threadIdx.x;

    const float rb  = rois[r * 5 + 0];
    const float rx1 = rois[r * 5 + 1] * SCALE;
    const float ry1 = rois[r * 5 + 2] * SCALE;
    const float rx2 = rois[r * 5 + 3] * SCALE;
    const float ry2 = rois[r * 5 + 4] * SCALE;
    const float bw = (rx2 - rx1) * (1.0f / POOLED);
    const float bh = (ry2 - ry1) * (1.0f / POOLED);
    const float area = bw * bh;
    const float sc = (area > 0.0f) ? (1.0f / fmaxf(area, 1e-12f)) : 0.0f;

    int wlo = (int)ceilf(rx1 - 1.0f); if (wlo < 0) wlo = 0;
    const int base4 = (wlo & ~3) >> 2;                    // <= 13
    int hlo = (int)ceilf(ry1 - 1.0f);  if (hlo < 0) hlo = 0;
    int hhi = (int)floorf(ry2 + 1.0f); if (hhi > HH - 1) hhi = HH - 1;
    if (hhi < hlo) hhi = hlo;

    // per-pair relative float4 offset within staged window (bounded <= 5)
    int prel[4];
#pragma unroll
    for (int g = 0; g < 4; ++g) {
        const float xs = rx1 + (2 * g) * bw;
        int pb = (int)ceilf(xs - 1.0f); if (pb < 0) pb = 0;
        int pb4 = (pb & ~3) >> 2; if (pb4 > 13) pb4 = 13;
        int rel = pb4 - base4;
        if (rel < 0) rel = 0;
        if (rel > 5) rel = 5;      // window rel..rel+2 fits NG=8 slots
        prel[g] = rel;
    }

    // x weights: 4 pairs x 2 bins x 12 taps (absolute w = (base4+prel)*4 + k)
    for (int e = t; e < 4 * 2 * 12; e += 32) {
        const int g = e / 24, rem = e - g * 24, bin = rem / 12, k = rem - bin * 12;
        const int q = 2 * g + bin;
        float v = 0.0f;
        if (q < POOLED) {
            const int w = (base4 + prel[g]) * 4 + k;
            if (w < WW) {
                const float xs = rx1 + q * bw;
                v = tent_int(xs, xs + bw, (float)w);
            }
        }
        g_ixw[r][g][bin][k] = v;
    }
    // y weights transposed: row-major by (h - hlo), 1/area folded, zero-padded
    for (int e = t; e < 28 * 8; e += 32) {
        const int hr = e >> 3, j = e & 7;
        const int h = hlo + hr;
        float v = 0.0f;
        if (j < POOLED && h <= hhi) {
            const float ys = ry1 + j * bh;
            v = sc * tent_int(ys, ys + bh, (float)h);
        }
        g_iyT[r][hr][j] = v;
    }
    if (t == 0) {
        g_meta[r][0] = (int)rb;
        g_meta[r][1] = hlo;
        g_meta[r][2] = hhi;
        g_meta[r][3] = base4;
        g_meta[r][4] = prel[0]; g_meta[r][5] = prel[1];
        g_meta[r][6] = prel[2]; g_meta[r][7] = prel[3];
    }
}

// ---------------- cp.async helpers ----------------
__device__ __forceinline__ void cpa16(uint32_t dst, const void* src) {
    asm volatile("cp.async.ca.shared.global [%0], [%1], 16;\n" :: "r"(dst), "l"(src));
}
__device__ __forceinline__ void cpa_commit() {
    asm volatile("cp.async.commit_group;\n");
}
template<int N>
__device__ __forceinline__ void cpa_wait() {
    asm volatile("cp.async.wait_group %0;\n" :: "n"(N));
}

// ---------------- main: 128 thr = 32 ch x 4 pw-pairs; grid = R*8 ----------------
__global__ __launch_bounds__(NTHR, 6)
void prroi_main(const float* __restrict__ feat, float* __restrict__ out) {
    const int bid = blockIdx.x;
    const int r    = bid >> 3;
    const int c0   = (bid & 7) << 5;          // 32-channel slab
    const int tid  = threadIdx.x;
    const int cl   = tid & 31;                // channel lane
    const int g    = tid >> 5;                // pw-pair group == warp id

    // 2 ping-pong buffers, each holding 2 feature rows
    __shared__ float4 sbuf[2][2][NCHS * NSTR];   // 4 x 288 x 16B = 18432 B

    const int4 m0 = __ldg((const int4*)&g_meta[r][0]);
    const int b = m0.x, hlo = m0.y, hhi = m0.z, base4 = m0.w;
    const int4 m1 = __ldg((const int4*)&g_meta[r][4]);
    const int prel = (g == 0) ? m1.x : (g == 1) ? m1.y : (g == 2) ? m1.z : m1.w;

    // hoist pair weights (2 bins x 12 taps) into registers (warp-uniform -> broadcast)
    float4 w0[3], w1[3];
    {
        const float4* wp = (const float4*)&g_ixw[r][g][0][0];
        w0[0] = __ldg(wp);     w0[1] = __ldg(wp + 1); w0[2] = __ldg(wp + 2);
        w1[0] = __ldg(wp + 3); w1[1] = __ldg(wp + 4); w1[2] = __ldg(wp + 5);
    }

    // staging: 256 slots (32 ch x 8 groups) in layout stride 9; 2 cp.async per thread/row
    const int c_lo = tid >> 3;                 // 0..15
    const int jj   = tid & 7;                  // group
    int i4 = base4 + jj; if (i4 > 13) i4 = 13; // clamp; weights are 0 for w>=56
    const float* s0p = feat + (size_t)(b * CC + c0 + c_lo) * (HH * WW) + i4 * 4;
    const float* s1p = s0p + 16 * (HH * WW);
    const uint32_t d0a = (uint32_t)__cvta_generic_to_shared(&sbuf[0][0][c_lo * NSTR + jj]);
    const uint32_t d1a = (uint32_t)__cvta_generic_to_shared(&sbuf[0][0][(c_lo + 16) * NSTR + jj]);
    const uint32_t rowB = NCHS * NSTR * 16;    // bytes per row slot
    const uint32_t bufB = 2 * rowB;            // bytes per ping-pong buffer

    // prologue: stage rows hlo, hlo+1 (clamped) into buffer 0 as one group
    {
        int h1 = hlo + 1; if (h1 > hhi) h1 = hhi;
        cpa16(d0a,        s0p + hlo * WW);
        cpa16(d1a,        s1p + hlo * WW);
        cpa16(d0a + rowB, s0p + h1 * WW);
        cpa16(d1a + rowB, s1p + h1 * WW);
        cpa_commit();
    }

    float acc0[POOLED], acc1[POOLED];
#pragma unroll
    for (int k = 0; k < POOLED; ++k) { acc0[k] = 0.0f; acc1[k] = 0.0f; }

    int p = 0;
    for (int h = hlo; h <= hhi; h += 2) {
        cpa_wait<0>();        // the single in-flight group (this iter's rows) done
        __syncthreads();      // visibility + all readers of buf p^1 finished

        // issue next iteration's rows (h+2, h+3 clamped) into buffer p^1
        if (h + 2 <= hhi) {
            int ha = h + 2;
            int hb = h + 3; if (hb > hhi) hb = hhi;
            const uint32_t off = (uint32_t)(p ^ 1) * bufB;
            cpa16(d0a + off,        s0p + ha * WW);
            cpa16(d1a + off,        s1p + ha * WW);
            cpa16(d0a + off + rowB, s0p + hb * WW);
            cpa16(d1a + off + rowB, s1p + hb * WW);
            cpa_commit();
        }

        // y weights for both rows (zero-padded table handles h+1 > hhi)
        const int hr = h - hlo;
        const float4 ya0 = __ldg((const float4*)&g_iyT[r][hr][0]);
        const float4 yb0 = __ldg((const float4*)&g_iyT[r][hr][4]);
        const float4 ya1 = __ldg((const float4*)&g_iyT[r][hr + 1][0]);
        const float4 yb1 = __ldg((const float4*)&g_iyT[r][hr + 1][4]);

#pragma unroll
        for (int rr = 0; rr < 2; ++rr) {
            const float4* xv = &sbuf[p][rr][cl * NSTR + prel];
            const float4 x0 = xv[0], x1 = xv[1], x2 = xv[2];

            float s0 = 0.0f, s1 = 0.0f;
            s0 = fmaf(x0.x, w0[0].x, s0); s0 = fmaf(x0.y, w0[0].y, s0);
            s0 = fmaf(x0.z, w0[0].z, s0); s0 = fmaf(x0.w, w0[0].w, s0);
            s0 = fmaf(x1.x, w0[1].x, s0); s0 = fmaf(x1.y, w0[1].y, s0);
            s0 = fmaf(x1.z, w0[1].z, s0); s0 = fmaf(x1.w, w0[1].w, s0);
            s0 = fmaf(x2.x, w0[2].x, s0); s0 = fmaf(x2.y, w0[2].y, s0);
            s0 = fmaf(x2.z, w0[2].z, s0); s0 = fmaf(x2.w, w0[2].w, s0);

            s1 = fmaf(x0.x, w1[0].x, s1); s1 = fmaf(x0.y, w1[0].y, s1);
            s1 = fmaf(x0.z, w1[0].z, s1); s1 = fmaf(x0.w, w1[0].w, s1);
            s1 = fmaf(x1.x, w1[1].x, s1); s1 = fmaf(x1.y, w1[1].y, s1);
            s1 = fmaf(x1.z, w1[1].z, s1); s1 = fmaf(x1.w, w1[1].w, s1);
            s1 = fmaf(x2.x, w1[2].x, s1); s1 = fmaf(x2.y, w1[2].y, s1);
            s1 = fmaf(x2.z, w1[2].z, s1); s1 = fmaf(x2.w, w1[2].w, s1);

            const float4 ya = rr ? ya1 : ya0;
            const float4 yb = rr ? yb1 : yb0;
            if (ya.x != 0.0f) { acc0[0] = fmaf(ya.x, s0, acc0[0]); acc1[0] = fmaf(ya.x, s1, acc1[0]); }
            if (ya.y != 0.0f) { acc0[1] = fmaf(ya.y, s0, acc0[1]); acc1[1] = fmaf(ya.y, s1, acc1[1]); }
            if (ya.z != 0.0f) { acc0[2] = fmaf(ya.z, s0, acc0[2]); acc1[2] = fmaf(ya.z, s1, acc1[2]); }
            if (ya.w != 0.0f) { acc0[3] = fmaf(ya.w, s0, acc0[3]); acc1[3] = fmaf(ya.w, s1, acc1[3]); }
            if (yb.x != 0.0f) { acc0[4] = fmaf(yb.x, s0, acc0[4]); acc1[4] = fmaf(yb.x, s1, acc1[4]); }
            if (yb.y != 0.0f) { acc0[5] = fmaf(yb.y, s0, acc0[5]); acc1[5] = fmaf(yb.y, s1, acc1[5]); }
            if (yb.z != 0.0f) { acc0[6] = fmaf(yb.z, s0, acc0[6]); acc1[6] = fmaf(yb.z, s1, acc1[6]); }
        }

        p ^= 1;
    }

    __syncthreads();   // all reads done before reusing smem for output gather

    // ---- gather to smem, write coalesced ----
    float* sout = (float*)&sbuf[0][0][0];     // 4608 floats >= 1568
    const int pw0 = 2 * g;
#pragma unroll
    for (int ph = 0; ph < POOLED; ++ph) {
        sout[cl * 49 + ph * 7 + pw0] = acc0[ph];
        if (pw0 + 1 < POOLED) sout[cl * 49 + ph * 7 + pw0 + 1] = acc1[ph];
    }
    __syncthreads();

    float4* o4 = (float4*)(out + ((size_t)r * CC + c0) * 49);
    const float4* s4 = (const float4*)sout;
#pragma unroll
    for (int k = 0; k < 3; ++k)
        o4[tid + NTHR * k] = s4[tid + NTHR * k];       // 384 float4
    if (tid < 8) o4[384 + tid] = s4[384 + tid];        // -> 392 = 1568 floats
}

extern "C" void kernel_launch(void* const* d_in, const int* in_sizes, int n_in,
                              void* d_out, int out_size) {
    const float* feat = (const float*)d_in[0];
    const float* rois = (const float*)d_in[1];
    float* out = (float*)d_out;
    int R = in_sizes[1] / 5;
    if (R > RMAX) R = RMAX;
    setup_kernel<<<R, 32>>>(rois, R);
    prroi_main<<<R * 8, NTHR>>>(feat, out);
}

// round 9
// speedup vs baseline: 1.1390x; 1.0654x over previous
#include <cuda_runtime.h>
#include <cuda_bf16.h>
#include <cstdint>

// PrRoIPool2D(7,7, spatial_scale=0.5)
// features: (8, 256, 56, 56) f32 ; rois: (256,5) ; out: (256,256,7,7) f32

#define POOLED 7
#define SCALE 0.5f
#define CC 256
#define HH 56
#define WW 56
#define RMAX 256
#define NG 8            // staged float4 groups per channel-row (32 floats >= 7bw+5)
#define NSTR 9          // smem layout stride in float4 (conflict-free LDS.128)
#define NCHS 32         // channels per CTA slab
#define NTHR 128        // 32 channels x 4 pw-pair groups

// ---- precomputed per-ROI tables ----
__device__ __align__(16) float g_ixw[RMAX][4][2][12]; // pair g, bin{2g,2g+1}, 12 taps
__device__ __align__(16) float g_iyT[RMAX][28][8];    // per-row (h-hlo): iy[7]*(1/area), pad
__device__ __align__(16) int   g_meta[RMAX][12];      // b,hlo,hhi,base4, prel[4], taps8flag

__device__ __forceinline__ float tentG(float t) {
    float u;
    if (t <= 0.0f) { u = t + 1.0f; return 0.5f * u * u; }
    u = 1.0f - t;
    return 1.0f - 0.5f * u * u;
}
__device__ __forceinline__ float tent_int(float s, float e, float i) {
    float a = fminf(fmaxf(s - i, -1.0f), 1.0f);
    float b = fminf(fmaxf(e - i, -1.0f), 1.0f);
    return tentG(b) - tentG(a);
}

// ---------------- setup: one 32-thread block per ROI ----------------
__global__ void setup_kernel(const float* __restrict__ rois, int R) {
    const int r = blockIdx.x;
    if (r >= R) return;
    const int t = threadIdx.x;

    const float rb  = rois[r * 5 + 0];
    const float rx1 = rois[r * 5 + 1] * SCALE;
    const float ry1 = rois[r * 5 + 2] * SCALE;
    const float rx2 = rois[r * 5 + 3] * SCALE;
    const float ry2 = rois[r * 5 + 4] * SCALE;
    const float bw = (rx2 - rx1) * (1.0f / POOLED);
    const float bh = (ry2 - ry1) * (1.0f / POOLED);
    const float area = bw * bh;
    const float sc = (area > 0.0f) ? (1.0f / fmaxf(area, 1e-12f)) : 0.0f;

    int wlo = (int)ceilf(rx1 - 1.0f); if (wlo < 0) wlo = 0;
    const int base4 = (wlo & ~3) >> 2;                    // <= 13
    int hlo = (int)ceilf(ry1 - 1.0f);  if (hlo < 0) hlo = 0;
    int hhi = (int)floorf(ry2 + 1.0f); if (hhi > HH - 1) hhi = HH - 1;
    if (hhi < hlo) hhi = hlo;

    // per-pair aligned base within staged window + 8-tap qualification
    int prel[4], ok8 = 1;
#pragma unroll
    for (int g = 0; g < 4; ++g) {
        const float xs = rx1 + (2 * g) * bw;
        int pb = (int)ceilf(xs - 1.0f); if (pb < 0) pb = 0;
        int pb4 = (pb & ~3) >> 2; if (pb4 > 13) pb4 = 13;
        int rel = pb4 - base4;
        if (rel < 0) rel = 0;
        if (rel > 5) rel = 5;      // window rel..rel+2 fits NG=8 slots
        prel[g] = rel;
        // last nonzero tap of this pair (pair 3 = bin 6 only)
        const float e = xs + ((g < 3) ? 2.0f * bw : bw);
        int whi = (int)floorf(e + 1.0f); if (whi > WW - 1) whi = WW - 1;
        if (whi - (base4 + rel) * 4 > 7) ok8 = 0;
    }

    // x weights: 4 pairs x 2 bins x 12 taps (absolute w = (base4+prel)*4 + k)
    for (int e = t; e < 4 * 2 * 12; e += 32) {
        const int g = e / 24, rem = e - g * 24, bin = rem / 12, k = rem - bin * 12;
        const int q = 2 * g + bin;
        float v = 0.0f;
        if (q < POOLED) {
            const int w = (base4 + prel[g]) * 4 + k;
            if (w < WW) {
                const float xs = rx1 + q * bw;
                v = tent_int(xs, xs + bw, (float)w);
            }
        }
        g_ixw[r][g][bin][k] = v;
    }
    // y weights transposed: row-major by (h - hlo), 1/area folded, zero-padded
    for (int e = t; e < 28 * 8; e += 32) {
        const int hr = e >> 3, j = e & 7;
        const int h = hlo + hr;
        float v = 0.0f;
        if (j < POOLED && h <= hhi) {
            const float ys = ry1 + j * bh;
            v = sc * tent_int(ys, ys + bh, (float)h);
        }
        g_iyT[r][hr][j] = v;
    }
    if (t == 0) {
        g_meta[r][0] = (int)rb;
        g_meta[r][1] = hlo;
        g_meta[r][2] = hhi;
        g_meta[r][3] = base4;
        g_meta[r][4] = prel[0]; g_meta[r][5] = prel[1];
        g_meta[r][6] = prel[2]; g_meta[r][7] = prel[3];
        g_meta[r][8] = ok8;
    }
}

// ---------------- cp.async helpers ----------------
__device__ __forceinline__ void cpa16(uint32_t dst, const void* src) {
    asm volatile("cp.async.ca.shared.global [%0], [%1], 16;\n" :: "r"(dst), "l"(src));
}
__device__ __forceinline__ void cpa_commit() {
    asm volatile("cp.async.commit_group;\n");
}
template<int N>
__device__ __forceinline__ void cpa_wait() {
    asm volatile("cp.async.wait_group %0;\n" :: "n"(N));
}

struct __align__(16) SmemT {
    float4 sbuf[2][2][NCHS * NSTR];   // 2 ping-pong bufs x 2 rows
    float  iy[28][8];                 // per-ROI y weights (1/area folded)
};

// ---- main loop body, templated on float4 groups per bin window (2 or 3) ----
template<int NJ>
__device__ __forceinline__ void run_loop(
    SmemT* sm, const float4* __restrict__ wp,
    const float* __restrict__ s0p, const float* __restrict__ s1p,
    uint32_t d0a, uint32_t d1a,
    int hlo, int hhi, int cl, int prel,
    float (&acc0)[POOLED], float (&acc1)[POOLED])
{
    const uint32_t rowB = NCHS * NSTR * 16;
    const uint32_t bufB = 2 * rowB;

    // pair weights in registers (warp-uniform -> broadcast LDG)
    float4 w0[NJ], w1[NJ];
#pragma unroll
    for (int m = 0; m < NJ; ++m) { w0[m] = __ldg(wp + m); w1[m] = __ldg(wp + 3 + m); }

    int p = 0;
    for (int h = hlo; h <= hhi; h += 2) {
        cpa_wait<0>();        // the single in-flight group (this iter's rows) done
        __syncthreads();      // visibility + all readers of buf p^1 finished

        // issue next iteration's rows (h+2, h+3 clamped) into buffer p^1
        if (h + 2 <= hhi) {
            int ha = h + 2;
            int hb = h + 3; if (hb > hhi) hb = hhi;
            const uint32_t off = (uint32_t)(p ^ 1) * bufB;
            cpa16(d0a + off,        s0p + ha * WW);
            cpa16(d1a + off,        s1p + ha * WW);
            cpa16(d0a + off + rowB, s0p + hb * WW);
            cpa16(d1a + off + rowB, s1p + hb * WW);
            cpa_commit();
        }

        // y weights for both rows from smem (broadcast LDS, zero-padded tail)
        const int hr = h - hlo;
        const float4 ya0 = *(const float4*)&sm->iy[hr][0];
        const float4 yb0 = *(const float4*)&sm->iy[hr][4];
        const float4 ya1 = *(const float4*)&sm->iy[hr + 1][0];
        const float4 yb1 = *(const float4*)&sm->iy[hr + 1][4];

#pragma unroll
        for (int rr = 0; rr < 2; ++rr) {
            const float4* xv = &sm->sbuf[p][rr][cl * NSTR + prel];
            float s0 = 0.0f, s1 = 0.0f;
#pragma unroll
            for (int j = 0; j < NJ; ++j) {
                const float4 x = xv[j];
                s0 = fmaf(x.x, w0[j].x, s0); s0 = fmaf(x.y, w0[j].y, s0);
                s0 = fmaf(x.z, w0[j].z, s0); s0 = fmaf(x.w, w0[j].w, s0);
                s1 = fmaf(x.x, w1[j].x, s1); s1 = fmaf(x.y, w1[j].y, s1);
                s1 = fmaf(x.z, w1[j].z, s1); s1 = fmaf(x.w, w1[j].w, s1);
            }
            const float4 ya = rr ? ya1 : ya0;
            const float4 yb = rr ? yb1 : yb0;
            if (ya.x != 0.0f) { acc0[0] = fmaf(ya.x, s0, acc0[0]); acc1[0] = fmaf(ya.x, s1, acc1[0]); }
            if (ya.y != 0.0f) { acc0[1] = fmaf(ya.y, s0, acc0[1]); acc1[1] = fmaf(ya.y, s1, acc1[1]); }
            if (ya.z != 0.0f) { acc0[2] = fmaf(ya.z, s0, acc0[2]); acc1[2] = fmaf(ya.z, s1, acc1[2]); }
            if (ya.w != 0.0f) { acc0[3] = fmaf(ya.w, s0, acc0[3]); acc1[3] = fmaf(ya.w, s1, acc1[3]); }
            if (yb.x != 0.0f) { acc0[4] = fmaf(yb.x, s0, acc0[4]); acc1[4] = fmaf(yb.x, s1, acc1[4]); }
            if (yb.y != 0.0f) { acc0[5] = fmaf(yb.y, s0, acc0[5]); acc1[5] = fmaf(yb.y, s1, acc1[5]); }
            if (yb.z != 0.0f) { acc0[6] = fmaf(yb.z, s0, acc0[6]); acc1[6] = fmaf(yb.z, s1, acc1[6]); }
        }
        p ^= 1;
    }
}

// ---------------- main: 128 thr = 32 ch x 4 pw-pairs; grid = R*8 ----------------
__global__ __launch_bounds__(NTHR, 6)
void prroi_main(const float* __restrict__ feat, float* __restrict__ out) {
    const int bid = blockIdx.x;
    const int r    = bid >> 3;
    const int c0   = (bid & 7) << 5;          // 32-channel slab
    const int tid  = threadIdx.x;
    const int cl   = tid & 31;                // channel lane
    const int g    = tid >> 5;                // pw-pair group == warp id

    __shared__ SmemT sm;

    const int4 m0 = __ldg((const int4*)&g_meta[r][0]);
    const int b = m0.x, hlo = m0.y, hhi = m0.z, base4 = m0.w;
    const int4 m1 = __ldg((const int4*)&g_meta[r][4]);
    const int prel = (g == 0) ? m1.x : (g == 1) ? m1.y : (g == 2) ? m1.z : m1.w;
    const int ok8 = __ldg(&g_meta[r][8]);

    // staging: 256 slots (32 ch x 8 groups) in layout stride 9; 2 cp.async per thread/row
    const int c_lo = tid >> 3;                 // 0..15
    const int jj   = tid & 7;                  // group
    int i4 = base4 + jj; if (i4 > 13) i4 = 13; // clamp; weights are 0 for w>=56
    const float* s0p = feat + (size_t)(b * CC + c0 + c_lo) * (HH * WW) + i4 * 4;
    const float* s1p = s0p + 16 * (HH * WW);
    const uint32_t d0a = (uint32_t)__cvta_generic_to_shared(&sm.sbuf[0][0][c_lo * NSTR + jj]);
    const uint32_t d1a = (uint32_t)__cvta_generic_to_shared(&sm.sbuf[0][0][(c_lo + 16) * NSTR + jj]);
    const uint32_t rowB = NCHS * NSTR * 16;

    // prologue: stage rows hlo, hlo+1 (clamped) into buffer 0 as one group
    {
        int h1 = hlo + 1; if (h1 > hhi) h1 = hhi;
        cpa16(d0a,        s0p + hlo * WW);
        cpa16(d1a,        s1p + hlo * WW);
        cpa16(d0a + rowB, s0p + h1 * WW);
        cpa16(d1a + rowB, s1p + h1 * WW);
        cpa_commit();
    }
    // copy this ROI's iy table into smem (one time; covered by loop's first barrier)
    if (tid < 56)
        ((float4*)&sm.iy[0][0])[tid] = __ldg((const float4*)&g_iyT[r][0][0] + tid);

    float acc0[POOLED], acc1[POOLED];
#pragma unroll
    for (int k = 0; k < POOLED; ++k) { acc0[k] = 0.0f; acc1[k] = 0.0f; }

    const float4* wp = (const float4*)&g_ixw[r][g][0][0];
    if (ok8) run_loop<2>(&sm, wp, s0p, s1p, d0a, d1a, hlo, hhi, cl, prel, acc0, acc1);
    else     run_loop<3>(&sm, wp, s0p, s1p, d0a, d1a, hlo, hhi, cl, prel, acc0, acc1);

    __syncthreads();   // all reads done before reusing smem for output gather

    // ---- gather to smem, write coalesced ----
    float* sout = (float*)&sm;                // plenty of room (>= 1568 floats)
    const int pw0 = 2 * g;
#pragma unroll
    for (int ph = 0; ph < POOLED; ++ph) {
        sout[cl * 49 + ph * 7 + pw0] = acc0[ph];
        if (pw0 + 1 < POOLED) sout[cl * 49 + ph * 7 + pw0 + 1] = acc1[ph];
    }
    __syncthreads();

    float4* o4 = (float4*)(out + ((size_t)r * CC + c0) * 49);
    const float4* s4 = (const float4*)sout;
#pragma unroll
    for (int k = 0; k < 3; ++k)
        o4[tid + NTHR * k] = s4[tid + NTHR * k];       // 384 float4
    if (tid < 8) o4[384 + tid] = s4[384 + tid];        // -> 392 = 1568 floats
}

extern "C" void kernel_launch(void* const* d_in, const int* in_sizes, int n_in,
                              void* d_out, int out_size) {
    const float* feat = (const float*)d_in[0];
    const float* rois = (const float*)d_in[1];
    float* out = (float*)d_out;
    int R = in_sizes[1] / 5;
    if (R > RMAX) R = RMAX;
    setup_kernel<<<R, 32>>>(rois, R);
    prroi_main<<<R * 8, NTHR>>>(feat, out);
}

// round 10
// speedup vs baseline: 1.3542x; 1.1889x over previous
#include <cuda_runtime.h>
#include <cuda_bf16.h>
#include <cstdint>

// PrRoIPool2D(7,7, spatial_scale=0.5)
// features: (8, 256, 56, 56) f32 ; rois: (256,5) ; out: (256,256,7,7) f32

#define POOLED 7
#define SCALE 0.5f
#define CC 256
#define HH 56
#define WW 56
#define NSTR 9          // smem layout stride in float4 (conflict-free LDS.128)
#define NCHS 32         // channels per CTA slab
#define NTHR 128        // 32 channels x 4 pw-pair groups

__device__ __forceinline__ float tentG(float t) {
    float u;
    if (t <= 0.0f) { u = t + 1.0f; return 0.5f * u * u; }
    u = 1.0f - t;
    return 1.0f - 0.5f * u * u;
}
__device__ __forceinline__ float tent_int(float s, float e, float i) {
    float a = fminf(fmaxf(s - i, -1.0f), 1.0f);
    float b = fminf(fmaxf(e - i, -1.0f), 1.0f);
    return tentG(b) - tentG(a);
}

// ---------------- cp.async helpers ----------------
__device__ __forceinline__ void cpa16(uint32_t dst, const void* src) {
    asm volatile("cp.async.ca.shared.global [%0], [%1], 16;\n" :: "r"(dst), "l"(src));
}
__device__ __forceinline__ void cpa_commit() {
    asm volatile("cp.async.commit_group;\n");
}
template<int N>
__device__ __forceinline__ void cpa_wait() {
    asm volatile("cp.async.wait_group %0;\n" :: "n"(N));
}

struct __align__(16) SmemT {
    float4 sbuf[2][2][NCHS * NSTR];   // 2 ping-pong bufs x 2 rows (18432 B)
    float  iy[28][8];                 // per-ROI y weights (1/area folded)
    float  ixw[4][2][12];             // pair g, bin{2g,2g+1}, 12 taps
};

// ---- whole unit: staging + table fill + main loop; NSB = staged groups, NJ = window groups ----
template<int NSB, int NJ>
__device__ __forceinline__ void run_unit(
    SmemT& sm, const float* __restrict__ feat,
    int b, int c0, int base4, int hlo, int hhi, int cl, int g, int prel,
    int p0, int p1, int p2, int p3, int tid,
    float rx1, float bw, float ry1, float bh, float sc,
    float (&acc0)[POOLED], float (&acc1)[POOLED])
{
    // slot mapping: 32*NSB slots; thread owns s=tid (+ s=tid+128 if present)
    const int s0c = tid / NSB, s0j = tid - s0c * NSB;
    int i40 = base4 + s0j; if (i40 > 13) i40 = 13;
    const float* src0 = feat + (size_t)(b * CC + c0 + s0c) * (HH * WW) + i40 * 4;
    const uint32_t dst0 =
        (uint32_t)__cvta_generic_to_shared(&sm.sbuf[0][0][s0c * NSTR + s0j]);

    const float* src1 = src0; uint32_t dst1 = dst0;
    bool have1 = false;
    if constexpr (NSB > 4) {
        const int s = tid + NTHR;
        if (s < NCHS * NSB) {          // NSB=8: always; NSB=6: warps 0-1 only
            const int c = s / NSB, j = s - c * NSB;
            int i4 = base4 + j; if (i4 > 13) i4 = 13;
            src1 = feat + (size_t)(b * CC + c0 + c) * (HH * WW) + i4 * 4;
            dst1 = (uint32_t)__cvta_generic_to_shared(&sm.sbuf[0][0][c * NSTR + j]);
            have1 = true;
        }
    }
    const uint32_t rowB = NCHS * NSTR * 16;
    const uint32_t bufB = 2 * rowB;

    // prologue: rows hlo, hlo+1 (clamped) into buffer 0 as one group
    {
        int h1 = hlo + 1; if (h1 > hhi) h1 = hhi;
        cpa16(dst0,        src0 + hlo * WW);
        cpa16(dst0 + rowB, src0 + h1 * WW);
        if constexpr (NSB > 4) {
            if (have1) {
                cpa16(dst1,        src1 + hlo * WW);
                cpa16(dst1 + rowB, src1 + h1 * WW);
            }
        }
        cpa_commit();
    }

    // ---- fill weight tables in smem (overlapped with prologue latency) ----
    if (tid < 96) {
        const int g4 = tid / 24, rem = tid - g4 * 24, bin = rem / 12, k = rem - bin * 12;
        const int pr = (g4 == 0) ? p0 : (g4 == 1) ? p1 : (g4 == 2) ? p2 : p3;
        const int q = 2 * g4 + bin;
        float v = 0.0f;
        if (q < POOLED) {
            const int w = (base4 + pr) * 4 + k;
            if (w < WW) {
                const float xs = rx1 + q * bw;
                v = tent_int(xs, xs + bw, (float)w);
            }
        }
        sm.ixw[g4][bin][k] = v;
    }
    for (int e = tid; e < 28 * 8; e += NTHR) {
        const int hr = e >> 3, j = e & 7;
        const int h = hlo + hr;
        float v = 0.0f;
        if (j < POOLED && h <= hhi) {
            const float ys = ry1 + j * bh;
            v = sc * tent_int(ys, ys + bh, (float)h);
        }
        sm.iy[hr][j] = v;
    }
    __syncthreads();   // tables visible

    // pair weights into registers (broadcast LDS)
    float4 w0[NJ], w1[NJ];
    const float4* wp = (const float4*)&sm.ixw[g][0][0];
#pragma unroll
    for (int m = 0; m < NJ; ++m) { w0[m] = wp[m]; w1[m] = wp[3 + m]; }

    int p = 0;
    for (int h = hlo; h <= hhi; h += 2) {
        cpa_wait<0>();        // single in-flight group (this iter's rows) done
        __syncthreads();      // visibility + readers of buf p^1 finished

        // issue next iteration's rows (h+2, h+3 clamped) into buffer p^1
        if (h + 2 <= hhi) {
            const int ha = h + 2;
            int hb = h + 3; if (hb > hhi) hb = hhi;
            const uint32_t off = (uint32_t)(p ^ 1) * bufB;
            cpa16(dst0 + off,        src0 + ha * WW);
            cpa16(dst0 + off + rowB, src0 + hb * WW);
            if constexpr (NSB > 4) {
                if (have1) {
                    cpa16(dst1 + off,        src1 + ha * WW);
                    cpa16(dst1 + off + rowB, src1 + hb * WW);
                }
            }
            cpa_commit();
        }

        // y weights for both rows from smem (broadcast LDS, zero-padded tail)
        const int hr = h - hlo;
        const float4 ya0 = *(const float4*)&sm.iy[hr][0];
        const float4 yb0 = *(const float4*)&sm.iy[hr][4];
        const float4 ya1 = *(const float4*)&sm.iy[hr + 1][0];
        const float4 yb1 = *(const float4*)&sm.iy[hr + 1][4];

#pragma unroll
        for (int rr = 0; rr < 2; ++rr) {
            const float4* xv = &sm.sbuf[p][rr][cl * NSTR + prel];
            float s0 = 0.0f, s1 = 0.0f;
#pragma unroll
            for (int j = 0; j < NJ; ++j) {
                const float4 x = xv[j];
                s0 = fmaf(x.x, w0[j].x, s0); s0 = fmaf(x.y, w0[j].y, s0);
                s0 = fmaf(x.z, w0[j].z, s0); s0 = fmaf(x.w, w0[j].w, s0);
                s1 = fmaf(x.x, w1[j].x, s1); s1 = fmaf(x.y, w1[j].y, s1);
                s1 = fmaf(x.z, w1[j].z, s1); s1 = fmaf(x.w, w1[j].w, s1);
            }
            const float4 ya = rr ? ya1 : ya0;
            const float4 yb = rr ? yb1 : yb0;
            if (ya.x != 0.0f) { acc0[0] = fmaf(ya.x, s0, acc0[0]); acc1[0] = fmaf(ya.x, s1, acc1[0]); }
            if (ya.y != 0.0f) { acc0[1] = fmaf(ya.y, s0, acc0[1]); acc1[1] = fmaf(ya.y, s1, acc1[1]); }
            if (ya.z != 0.0f) { acc0[2] = fmaf(ya.z, s0, acc0[2]); acc1[2] = fmaf(ya.z, s1, acc1[2]); }
            if (ya.w != 0.0f) { acc0[3] = fmaf(ya.w, s0, acc0[3]); acc1[3] = fmaf(ya.w, s1, acc1[3]); }
            if (yb.x != 0.0f) { acc0[4] = fmaf(yb.x, s0, acc0[4]); acc1[4] = fmaf(yb.x, s1, acc1[4]); }
            if (yb.y != 0.0f) { acc0[5] = fmaf(yb.y, s0, acc0[5]); acc1[5] = fmaf(yb.y, s1, acc1[5]); }
            if (yb.z != 0.0f) { acc0[6] = fmaf(yb.z, s0, acc0[6]); acc1[6] = fmaf(yb.z, s1, acc1[6]); }
        }
        p ^= 1;
    }
}

// ---------------- single fused kernel: 128 thr = 32 ch x 4 pw-pairs; grid = R*8 ----------------
__global__ __launch_bounds__(NTHR, 6)
void prroi_main(const float* __restrict__ feat, const float* __restrict__ rois,
                float* __restrict__ out)
{
    const int bid = blockIdx.x;
    const int r    = bid >> 3;
    const int c0   = (bid & 7) << 5;          // 32-channel slab
    const int tid  = threadIdx.x;
    const int cl   = tid & 31;                // channel lane
    const int g    = tid >> 5;                // pw-pair group == warp id

    __shared__ SmemT sm;

    // ---- per-ROI meta (uniform, redundant per thread; broadcast loads) ----
    const float rb  = __ldg(&rois[r * 5 + 0]);
    const float rx1 = __ldg(&rois[r * 5 + 1]) * SCALE;
    const float ry1 = __ldg(&rois[r * 5 + 2]) * SCALE;
    const float rx2 = __ldg(&rois[r * 5 + 3]) * SCALE;
    const float ry2 = __ldg(&rois[r * 5 + 4]) * SCALE;
    const int   b   = (int)rb;
    const float bw = (rx2 - rx1) * (1.0f / POOLED);
    const float bh = (ry2 - ry1) * (1.0f / POOLED);
    const float area = bw * bh;
    const float sc = (area > 0.0f) ? (1.0f / fmaxf(area, 1e-12f)) : 0.0f;

    int wlo = (int)ceilf(rx1 - 1.0f); if (wlo < 0) wlo = 0;
    const int base4 = (wlo & ~3) >> 2;                    // <= 13
    int hlo = (int)ceilf(ry1 - 1.0f);  if (hlo < 0) hlo = 0;
    int hhi = (int)floorf(ry2 + 1.0f); if (hhi > HH - 1) hhi = HH - 1;
    if (hhi < hlo) hhi = hlo;

    // per-pair relative float4 base within staged window + 8-tap qualification
    int pr[4]; int ok8 = 1;
#pragma unroll
    for (int gg = 0; gg < 4; ++gg) {
        const float xs = rx1 + (2 * gg) * bw;
        int pb = (int)ceilf(xs - 1.0f); if (pb < 0) pb = 0;
        int pb4 = (pb & ~3) >> 2; if (pb4 > 13) pb4 = 13;
        int rel = pb4 - base4;
        if (rel < 0) rel = 0;
        if (rel > 5) rel = 5;
        pr[gg] = rel;
        const float e = xs + ((gg < 3) ? 2.0f * bw : bw);
        int whi = (int)floorf(e + 1.0f); if (whi > WW - 1) whi = WW - 1;
        if (whi - (base4 + rel) * 4 > 7) ok8 = 0;
    }
    const int p0 = pr[0], p1 = pr[1], p2 = pr[2], p3 = pr[3];
    const int prel = (g == 0) ? p0 : (g == 1) ? p1 : (g == 2) ? p2 : p3;
    const int NSx = p3 + 3;                   // exact staged-group need (<= 8)

    float acc0[POOLED], acc1[POOLED];
#pragma unroll
    for (int k = 0; k < POOLED; ++k) { acc0[k] = 0.0f; acc1[k] = 0.0f; }

    if (ok8) {
        if (NSx <= 4)      run_unit<4, 2>(sm, feat, b, c0, base4, hlo, hhi, cl, g, prel, p0, p1, p2, p3, tid, rx1, bw, ry1, bh, sc, acc0, acc1);
        else if (NSx <= 6) run_unit<6, 2>(sm, feat, b, c0, base4, hlo, hhi, cl, g, prel, p0, p1, p2, p3, tid, rx1, bw, ry1, bh, sc, acc0, acc1);
        else               run_unit<8, 2>(sm, feat, b, c0, base4, hlo, hhi, cl, g, prel, p0, p1, p2, p3, tid, rx1, bw, ry1, bh, sc, acc0, acc1);
    } else {
        if (NSx <= 4)      run_unit<4, 3>(sm, feat, b, c0, base4, hlo, hhi, cl, g, prel, p0, p1, p2, p3, tid, rx1, bw, ry1, bh, sc, acc0, acc1);
        else if (NSx <= 6) run_unit<6, 3>(sm, feat, b, c0, base4, hlo, hhi, cl, g, prel, p0, p1, p2, p3, tid, rx1, bw, ry1, bh, sc, acc0, acc1);
        else               run_unit<8, 3>(sm, feat, b, c0, base4, hlo, hhi, cl, g, prel, p0, p1, p2, p3, tid, rx1, bw, ry1, bh, sc, acc0, acc1);
    }

    __syncthreads();   // all reads done before reusing smem for output gather

    // ---- gather to smem, write coalesced ----
    float* sout = (float*)&sm;                // plenty of room (>= 1568 floats)
    const int pw0 = 2 * g;
#pragma unroll
    for (int ph = 0; ph < POOLED; ++ph) {
        sout[cl * 49 + ph * 7 + pw0] = acc0[ph];
        if (pw0 + 1 < POOLED) sout[cl * 49 + ph * 7 + pw0 + 1] = acc1[ph];
    }
    __syncthreads();

    float4* o4 = (float4*)(out + ((size_t)r * CC + c0) * 49);
    const float4* s4 = (const float4*)sout;
#pragma unroll
    for (int k = 0; k < 3; ++k)
        o4[tid + NTHR * k] = s4[tid + NTHR * k];       // 384 float4
    if (tid < 8) o4[384 + tid] = s4[384 + tid];        // -> 392 = 1568 floats
}

extern "C" void kernel_launch(void* const* d_in, const int* in_sizes, int n_in,
                              void* d_out, int out_size) {
    const float* feat = (const float*)d_in[0];
    const float* rois = (const float*)d_in[1];
    float* out = (float*)d_out;
    const int R = in_sizes[1] / 5;
    prroi_main<<<R * 8, NTHR>>>(feat, rois, out);
}